// round 1
// baseline (speedup 1.0000x reference)
#include <cuda_runtime.h>
#include <cuda_bf16.h>

// Device-global accumulator (no allocations allowed).
__device__ double g_acc;

__global__ void zero_kernel() {
    g_acc = 0.0;
}

// Focal loss for one 2-class row, 3 MUFU ops total.
// loss = -(oh0 * lp0 * p1^2 + oh1 * lp1 * p0^2)
// with oh1 = t*0.25, oh0 = (1-oh1)*0.75, t = (g >= 0.5)
__device__ __forceinline__ float row_loss(float p0, float p1, float g) {
    float d   = p1 - p0;
    float ad  = fabsf(d);
    float e   = __expf(-ad);              // MUFU 1
    float opl = 1.0f + e;
    float l1p = __logf(opl);              // MUFU 2  (= log1p(e), e<=1 so well-conditioned)
    float r   = __frcp_rn(opl);           // MUFU 3  (= 1/(1+e))

    float lp_big   = -l1p;                // log-prob of the larger logit
    float lp_small = -ad - l1p;           // log-prob of the smaller logit
    float pr_big   = r;
    float pr_small = e * r;

    bool one_is_big = (d >= 0.0f);
    float lp1 = one_is_big ? lp_big   : lp_small;
    float lp0 = one_is_big ? lp_small : lp_big;
    float pr1 = one_is_big ? pr_big   : pr_small;
    float pr0 = 1.0f - pr1;

    float t   = (g >= 0.5f) ? 1.0f : 0.0f;
    float oh1 = t * 0.25f;
    float oh0 = (1.0f - oh1) * 0.75f;

    // focal0 = (1-pr0)^2 = pr1^2 ; focal1 = (1-pr1)^2 = pr0^2
    return -(oh0 * lp0 * pr1 * pr1 + oh1 * lp1 * pr0 * pr0);
}

__global__ void __launch_bounds__(256)
focal_kernel(const float4* __restrict__ pred4,
             const float4* __restrict__ gold4,
             int nquads, int nrows)
{
    float acc = 0.0f;
    int stride = gridDim.x * blockDim.x;
    int gid = blockIdx.x * blockDim.x + threadIdx.x;

    // 4 rows per iteration: two float4 from pred, one float4 from gold.
    for (int i = gid; i < nquads; i += stride) {
        float4 pa = pred4[2 * i];
        float4 pb = pred4[2 * i + 1];
        float4 gg = gold4[i];
        acc += row_loss(pa.x, pa.y, gg.x);
        acc += row_loss(pa.z, pa.w, gg.y);
        acc += row_loss(pb.x, pb.y, gg.z);
        acc += row_loss(pb.z, pb.w, gg.w);
    }

    // Scalar tail (nrows not divisible by 4) handled by global thread 0.
    if (gid == 0) {
        const float* pred = (const float*)pred4;
        const float* gold = (const float*)gold4;
        for (int rw = nquads * 4; rw < nrows; rw++) {
            acc += row_loss(pred[2 * rw], pred[2 * rw + 1], gold[rw]);
        }
    }

    // Warp reduction
    #pragma unroll
    for (int o = 16; o > 0; o >>= 1)
        acc += __shfl_xor_sync(0xffffffff, acc, o);

    __shared__ float warp_sums[8];
    int lane = threadIdx.x & 31;
    int wid  = threadIdx.x >> 5;
    if (lane == 0) warp_sums[wid] = acc;
    __syncthreads();

    if (wid == 0) {
        float v = (lane < (blockDim.x >> 5)) ? warp_sums[lane] : 0.0f;
        #pragma unroll
        for (int o = 4; o > 0; o >>= 1)
            v += __shfl_xor_sync(0xffffffff, v, o);
        if (lane == 0)
            atomicAdd(&g_acc, (double)v);
    }
}

__global__ void finish_kernel(float* out) {
    out[0] = (float)g_acc;   // CORR = 1.0
}

extern "C" void kernel_launch(void* const* d_in, const int* in_sizes, int n_in,
                              void* d_out, int out_size) {
    const float4* pred4 = (const float4*)d_in[0];   // [N, 2] f32
    const float4* gold4 = (const float4*)d_in[1];   // [N]    f32
    float* out = (float*)d_out;

    int nrows  = in_sizes[1];       // N
    int nquads = nrows >> 2;        // rows processed 4-at-a-time

    zero_kernel<<<1, 1>>>();
    focal_kernel<<<2048, 256>>>(pred4, gold4, nquads, nrows);
    finish_kernel<<<1, 1>>>(out);
}